// round 1
// baseline (speedup 1.0000x reference)
#include <cuda_runtime.h>

#define NB    32
#define NN    8192
#define NCLIP 256
#define CAP   2048   // per-batch capacity; E[count]=256, sd~16 -> overflow prob ~0

// Scratch (allocation-free rule: __device__ globals)
__device__ float g_ss[NN];   // sorted start
__device__ float g_se[NN];   // sorted end
__device__ float g_sc[NN];   // sorted score
__device__ int   g_sb[NN];   // sorted batch id

// ---------------------------------------------------------------------------
// Kernel 1: gt_dist[b, c, k] = exp(-(c - 256*center_k)^2 / (2*(alpha_k*len)^2))
// centers: 256*s, 256*e, 256*(s+e)/2 ; len = 256*(e-s); alpha = {.25,.25,.21}
// ---------------------------------------------------------------------------
__global__ void gt_dist_kernel(const float* __restrict__ gt,
                               float* __restrict__ out) {
    int b = blockIdx.x;      // 0..31
    int c = threadIdx.x;     // 0..255
    float s = gt[2 * b];
    float e = gt[2 * b + 1];
    float len  = 256.0f * (e - s);
    float cen0 = 256.0f * s;
    float cen1 = 256.0f * e;
    float cen2 = 128.0f * (s + e);
    float sgS  = 0.25f * len;   // sigma for start/end
    float sgM  = 0.21f * len;   // sigma for mid
    float inv2sS = 1.0f / (2.0f * sgS * sgS);
    float inv2sM = 1.0f / (2.0f * sgM * sgM);
    float fc = (float)c;
    float d0 = fc - cen0;
    float d1 = fc - cen1;
    float d2 = fc - cen2;
    float* o = out + ((size_t)b * NCLIP + c) * 3;
    o[0] = expf(-d0 * d0 * inv2sS);
    o[1] = expf(-d1 * d1 * inv2sS);
    o[2] = expf(-d2 * d2 * inv2sM);
}

// ---------------------------------------------------------------------------
// Kernel 2: stable descending rank by counting, then scatter into sorted arrays.
// rank[i] = #{j : score[j] > score[i]} + #{j < i : score[j] == score[i]}
// Exactly reproduces jnp.argsort(-score) (stable) as a bijection.
// ---------------------------------------------------------------------------
__global__ void rank_scatter_kernel(const float* __restrict__ pred,
                                    const float* __restrict__ score,
                                    const int*   __restrict__ bidx) {
    int i = blockIdx.x * blockDim.x + threadIdx.x;   // 0..8191
    float si = score[i];
    const float4* s4 = (const float4*)score;
    int r = 0;
#pragma unroll 4
    for (int j4 = 0; j4 < NN / 4; j4++) {
        float4 v = s4[j4];
        int j = j4 * 4;
        r += (v.x > si) || (v.x == si && (j + 0) < i);
        r += (v.y > si) || (v.y == si && (j + 1) < i);
        r += (v.z > si) || (v.z == si && (j + 2) < i);
        r += (v.w > si) || (v.w == si && (j + 3) < i);
    }
    g_ss[r] = pred[2 * i];
    g_se[r] = pred[2 * i + 1];
    g_sc[r] = si;
    g_sb[r] = bidx[i];
}

// ---------------------------------------------------------------------------
// Kernel 3: per-batch greedy NMS. One CTA per batch.
//  Phase A: order-preserving compaction of this batch's entries from the
//           globally sorted list (ballot + popc prefix).
//  Phase B: greedy suppression (sequential over i, parallel over j).
//  Phase C: write masked boxes/scores at global sorted positions.
// ---------------------------------------------------------------------------
__global__ void nms_kernel(float* __restrict__ out) {
    __shared__ float ls[CAP];
    __shared__ float le[CAP];
    __shared__ int   lpos[CAP];
    __shared__ int   keep[CAP];
    __shared__ int   wcnt[8];

    int b    = blockIdx.x;
    int tid  = threadIdx.x;           // 0..255
    int lane = tid & 31;
    int wid  = tid >> 5;

    // Phase A: compaction
    int running = 0;
    for (int base = 0; base < NN; base += 256) {
        int i = base + tid;
        bool p = (g_sb[i] == b);
        unsigned msk = __ballot_sync(0xffffffffu, p);
        if (lane == 0) wcnt[wid] = __popc(msk);
        __syncthreads();
        int wbase = 0;
#pragma unroll
        for (int w = 0; w < 8; w++)
            if (w < wid) wbase += wcnt[w];
        if (p) {
            int pos = running + wbase + __popc(msk & ((1u << lane) - 1));
            if (pos < CAP) {
                ls[pos]   = g_ss[i];
                le[pos]   = g_se[i];
                lpos[pos] = i;
                keep[pos] = 1;
            }
        }
        int tot = 0;
#pragma unroll
        for (int w = 0; w < 8; w++) tot += wcnt[w];
        running += tot;
        __syncthreads();   // protect wcnt before next chunk rewrites it
    }
    int mtot = running < CAP ? running : CAP;

    // Phase B: greedy suppression
    for (int i = 0; i < mtot; i++) {
        if (keep[i]) {
            float si = ls[i], ei = le[i], li = ei - si;
            for (int j = i + 1 + tid; j < mtot; j += 256) {
                if (keep[j]) {
                    float inter = fmaxf(fminf(ei, le[j]) - fmaxf(si, ls[j]), 0.0f);
                    float uni   = li + (le[j] - ls[j]) - inter;
                    float iou   = inter / fmaxf(uni, 1e-8f);
                    if (iou > 0.5f) keep[j] = 0;
                }
            }
        }
        __syncthreads();
    }

    // Phase C: scatter masked outputs
    float* ob = out + (size_t)NB * NCLIP * 3;   // nms_pred_bds [8192,2]
    float* os = ob + 2 * NN;                    // nms_score    [8192]
    for (int k = tid; k < mtot; k += 256) {
        int p   = lpos[k];
        float f = keep[k] ? 1.0f : 0.0f;
        ob[2 * p]     = ls[k] * f;
        ob[2 * p + 1] = le[k] * f;
        os[p]         = g_sc[p] * f;
    }
}

// ---------------------------------------------------------------------------
extern "C" void kernel_launch(void* const* d_in, const int* in_sizes, int n_in,
                              void* d_out, int out_size) {
    const float* gt    = (const float*)d_in[0];   // [32,2]
    const float* pred  = (const float*)d_in[1];   // [8192,2]
    const float* score = (const float*)d_in[2];   // [8192]
    const int*   bidx  = (const int*)d_in[3];     // [8192]
    float* out = (float*)d_out;                   // 49152 f32

    gt_dist_kernel<<<NB, NCLIP>>>(gt, out);
    rank_scatter_kernel<<<32, 256>>>(pred, score, bidx);
    nms_kernel<<<NB, 256>>>(out);
}

// round 2
// speedup vs baseline: 1.6337x; 1.6337x over previous
#include <cuda_runtime.h>

#define NB    32
#define NN    8192
#define NCLIP 256
#define JCH   16          // j-chunks for partial rank
#define JSZ   (NN / JCH)  // 512
#define CAPB  512         // per-batch capacity (mean 256, sd ~16 -> 16 sigma margin)
#define SLOTS (CAPB / 32) // 16 register slots per lane

// Scratch (__device__ globals; allocation-free rule)
__device__ int   g_off[NB + 1];        // batch -> original-index range
__device__ int   g_part[JCH * NN];     // partial global ranks
__device__ float g_bs[NB * CAPB];      // per-batch sorted start
__device__ float g_be[NB * CAPB];      // per-batch sorted end
__device__ float g_bsc[NB * CAPB];     // per-batch sorted score
__device__ int   g_bgr[NB * CAPB];     // global rank of each batch entry

// ---------------------------------------------------------------------------
// Kernel 1: blocks 0..31 -> gt_dist ; blocks 32..63 -> batch offsets g_off
// ---------------------------------------------------------------------------
__global__ void prep_kernel(const float* __restrict__ gt,
                            const int*   __restrict__ bidx,
                            float* __restrict__ out) {
    int blk = blockIdx.x;
    if (blk < NB) {
        int b = blk, c = threadIdx.x;
        float s = gt[2 * b];
        float e = gt[2 * b + 1];
        float len  = 256.0f * (e - s);
        float cen0 = 256.0f * s;
        float cen1 = 256.0f * e;
        float cen2 = 128.0f * (s + e);
        float sgS  = 0.25f * len;
        float sgM  = 0.21f * len;
        float inv2sS = 1.0f / (2.0f * sgS * sgS);
        float inv2sM = 1.0f / (2.0f * sgM * sgM);
        float fc = (float)c;
        float d0 = fc - cen0, d1 = fc - cen1, d2 = fc - cen2;
        float* o = out + ((size_t)b * NCLIP + c) * 3;
        o[0] = expf(-d0 * d0 * inv2sS);
        o[1] = expf(-d1 * d1 * inv2sS);
        o[2] = expf(-d2 * d2 * inv2sM);
    } else {
        int i = (blk - NB) * 256 + threadIdx.x;        // 0..8191
        int b  = bidx[i];
        int pb = (i == 0) ? -1 : bidx[i - 1];
        for (int x = pb + 1; x <= b; x++) g_off[x] = i; // handles empty batches
        if (i == NN - 1)
            for (int x = b + 1; x <= NB; x++) g_off[x] = NN;
    }
}

// ---------------------------------------------------------------------------
// Kernel 2: partial global rank. blockIdx.x = j-chunk, blockIdx.y = i-block.
// rank contribution over j in [jc*512, jc*512+512).
// ---------------------------------------------------------------------------
__global__ void rank_partial_kernel(const float* __restrict__ score) {
    int jc = blockIdx.x;                              // 0..15
    int i  = blockIdx.y * 256 + threadIdx.x;          // 0..8191
    float si = score[i];
    const float4* s4 = (const float4*)score + jc * (JSZ / 4);
    int jbase = jc * JSZ;
    int r = 0;
#pragma unroll 8
    for (int t = 0; t < JSZ / 4; t++) {
        float4 v = s4[t];
        int j = jbase + 4 * t;
        r += (v.x > si) || (v.x == si && (j + 0) < i);
        r += (v.y > si) || (v.y == si && (j + 1) < i);
        r += (v.z > si) || (v.z == si && (j + 2) < i);
        r += (v.w > si) || (v.w == si && (j + 3) < i);
    }
    g_part[jc * NN + i] = r;
}

// ---------------------------------------------------------------------------
// Kernel 3: finalize ranks, compute within-batch rank, scatter to batch arrays.
// ---------------------------------------------------------------------------
__global__ void scatter_kernel(const float* __restrict__ pred,
                               const float* __restrict__ score,
                               const int*   __restrict__ bidx) {
    int i = blockIdx.x * 256 + threadIdx.x;
    int r = 0;
#pragma unroll
    for (int jc = 0; jc < JCH; jc++) r += g_part[jc * NN + i];

    float si = score[i];
    int b  = bidx[i];
    int ob = g_off[b], oe = g_off[b + 1];
    int wr = 0;
    for (int j = ob; j < oe; j++) {
        float sj = score[j];
        wr += (sj > si) || (sj == si && j < i);
    }
    if (wr < CAPB) {
        int p = b * CAPB + wr;
        g_bs[p]  = pred[2 * i];
        g_be[p]  = pred[2 * i + 1];
        g_bsc[p] = si;
        g_bgr[p] = r;
    }
}

// ---------------------------------------------------------------------------
// Kernel 4: barrier-free greedy NMS, one warp per batch, boxes in registers.
// Box g = slot*32 + lane (interleaved). keep = 16-bit mask per lane.
// ---------------------------------------------------------------------------
__global__ void nms_kernel(float* __restrict__ out) {
    int b    = blockIdx.x;
    int lane = threadIdx.x;   // 0..31
    int cnt  = g_off[b + 1] - g_off[b];
    if (cnt > CAPB) cnt = CAPB;

    float s[SLOTS], e[SLOTS];
    unsigned keep = 0;
#pragma unroll
    for (int t = 0; t < SLOTS; t++) {
        int idx = t * 32 + lane;
        if (idx < cnt) {
            s[t] = g_bs[b * CAPB + idx];
            e[t] = g_be[b * CAPB + idx];
            keep |= 1u << t;
        } else { s[t] = 0.0f; e[t] = 0.0f; }
    }

#pragma unroll
    for (int so = 0; so < SLOTS; so++) {
        if (so * 32 >= cnt) break;                 // warp-uniform
        for (int ls = 0; ls < 32; ls++) {
            int i = so * 32 + ls;
            unsigned kw = __shfl_sync(0xffffffffu, keep, ls);
            if (!((kw >> so) & 1)) continue;       // warp-uniform: box i dead/absent
            float si = __shfl_sync(0xffffffffu, s[so], ls);
            float ei = __shfl_sync(0xffffffffu, e[so], ls);
            float li = ei - si;
#pragma unroll
            for (int t = so; t < SLOTS; t++) {
                int idx = t * 32 + lane;
                if (idx > i && ((keep >> t) & 1)) {
                    float inter = fmaxf(fminf(ei, e[t]) - fmaxf(si, s[t]), 0.0f);
                    float uni   = li + (e[t] - s[t]) - inter;
                    float iou   = inter / fmaxf(uni, 1e-8f);
                    if (iou > 0.5f) keep &= ~(1u << t);
                }
            }
        }
    }

    // Write masked outputs at global sorted positions
    float* obds = out + (size_t)NB * NCLIP * 3;   // [8192,2]
    float* osc  = obds + 2 * NN;                  // [8192]
#pragma unroll
    for (int t = 0; t < SLOTS; t++) {
        int idx = t * 32 + lane;
        if (idx < cnt) {
            int p = b * CAPB + idx;
            int g = g_bgr[p];
            float f = ((keep >> t) & 1) ? 1.0f : 0.0f;
            obds[2 * g]     = g_bs[p] * f;
            obds[2 * g + 1] = g_be[p] * f;
            osc[g]          = g_bsc[p] * f;
        }
    }
}

// ---------------------------------------------------------------------------
extern "C" void kernel_launch(void* const* d_in, const int* in_sizes, int n_in,
                              void* d_out, int out_size) {
    const float* gt    = (const float*)d_in[0];
    const float* pred  = (const float*)d_in[1];
    const float* score = (const float*)d_in[2];
    const int*   bidx  = (const int*)d_in[3];
    float* out = (float*)d_out;

    prep_kernel<<<2 * NB, 256>>>(gt, bidx, out);
    rank_partial_kernel<<<dim3(JCH, NN / 256), 256>>>(score);
    scatter_kernel<<<NN / 256, 256>>>(pred, score, bidx);
    nms_kernel<<<NB, 32>>>(out);
}

// round 4
// speedup vs baseline: 1.7145x; 1.0495x over previous
#include <cuda_runtime.h>

#define NB    32
#define NN    8192
#define NCLIP 256
#define JCH   16          // j-chunks for partial rank
#define JSZ   (NN / JCH)  // 512
#define CAPB  512         // per-batch capacity (mean 256, sd ~16)
#define SLOTS (CAPB / 32) // 16 register slots per lane
#define FULL  0xffffffffu

// Scratch (__device__ globals; allocation-free rule)
__device__ int   g_off[NB + 1];
__device__ int   g_part[JCH * NN];
__device__ float g_bs[NB * CAPB];
__device__ float g_be[NB * CAPB];
__device__ float g_bsc[NB * CAPB];
__device__ int   g_bgr[NB * CAPB];

// ---------------------------------------------------------------------------
// Kernel 1: blocks 0..31 -> gt_dist ; blocks 32..63 -> batch offsets g_off
// ---------------------------------------------------------------------------
__global__ void prep_kernel(const float* __restrict__ gt,
                            const int*   __restrict__ bidx,
                            float* __restrict__ out) {
    int blk = blockIdx.x;
    if (blk < NB) {
        int b = blk, c = threadIdx.x;
        float s = gt[2 * b];
        float e = gt[2 * b + 1];
        float len  = 256.0f * (e - s);
        float cen0 = 256.0f * s;
        float cen1 = 256.0f * e;
        float cen2 = 128.0f * (s + e);
        float sgS  = 0.25f * len;
        float sgM  = 0.21f * len;
        float inv2sS = 1.0f / (2.0f * sgS * sgS);
        float inv2sM = 1.0f / (2.0f * sgM * sgM);
        float fc = (float)c;
        float d0 = fc - cen0, d1 = fc - cen1, d2 = fc - cen2;
        float* o = out + ((size_t)b * NCLIP + c) * 3;
        o[0] = expf(-d0 * d0 * inv2sS);
        o[1] = expf(-d1 * d1 * inv2sS);
        o[2] = expf(-d2 * d2 * inv2sM);
    } else {
        int i = (blk - NB) * 256 + threadIdx.x;
        int b  = bidx[i];
        int pb = (i == 0) ? -1 : bidx[i - 1];
        for (int x = pb + 1; x <= b; x++) g_off[x] = i;
        if (i == NN - 1)
            for (int x = b + 1; x <= NB; x++) g_off[x] = NN;
    }
}

// ---------------------------------------------------------------------------
// Kernel 2: partial global rank over j-chunk jc.
// ---------------------------------------------------------------------------
__global__ void rank_partial_kernel(const float* __restrict__ score) {
    int jc = blockIdx.x;
    int i  = blockIdx.y * 256 + threadIdx.x;
    float si = score[i];
    const float4* s4 = (const float4*)score + jc * (JSZ / 4);
    int jbase = jc * JSZ;
    int r = 0;
#pragma unroll 8
    for (int t = 0; t < JSZ / 4; t++) {
        float4 v = s4[t];
        int j = jbase + 4 * t;
        r += (v.x > si) || (v.x == si && (j + 0) < i);
        r += (v.y > si) || (v.y == si && (j + 1) < i);
        r += (v.z > si) || (v.z == si && (j + 2) < i);
        r += (v.w > si) || (v.w == si && (j + 3) < i);
    }
    g_part[jc * NN + i] = r;
}

// ---------------------------------------------------------------------------
// Kernel 3: finalize ranks, within-batch rank, scatter to batch arrays.
// ---------------------------------------------------------------------------
__global__ void scatter_kernel(const float* __restrict__ pred,
                               const float* __restrict__ score,
                               const int*   __restrict__ bidx) {
    int i = blockIdx.x * 256 + threadIdx.x;
    int r = 0;
#pragma unroll
    for (int jc = 0; jc < JCH; jc++) r += g_part[jc * NN + i];

    float si = score[i];
    int b  = bidx[i];
    int ob = g_off[b], oe = g_off[b + 1];
    int wr = 0;
    for (int j = ob; j < oe; j++) {
        float sj = score[j];
        wr += (sj > si) || (sj == si && j < i);
    }
    if (wr < CAPB) {
        int p = b * CAPB + wr;
        g_bs[p]  = pred[2 * i];
        g_be[p]  = pred[2 * i + 1];
        g_bsc[p] = si;
        g_bgr[p] = r;
    }
}

// ---------------------------------------------------------------------------
// Kernel 4: warp-per-batch greedy NMS, survivor-only ballot iteration,
// dynamic slot count, boxes in registers.
// ---------------------------------------------------------------------------
__global__ void nms_kernel(float* __restrict__ out) {
    int b    = blockIdx.x;
    int lane = threadIdx.x;
    int cnt  = g_off[b + 1] - g_off[b];
    if (cnt > CAPB) cnt = CAPB;
    int nslots = (cnt + 31) >> 5;

    float s[SLOTS], e[SLOTS];
    unsigned keep = 0;
#pragma unroll
    for (int t = 0; t < SLOTS; t++) {
        if (t >= nslots) break;
        int idx = t * 32 + lane;
        if (idx < cnt) {
            s[t] = g_bs[b * CAPB + idx];
            e[t] = g_be[b * CAPB + idx];
            keep |= 1u << t;
        } else { s[t] = 0.0f; e[t] = 0.0f; }
    }

    for (int so = 0; so < nslots; so++) {
        unsigned surv = __ballot_sync(FULL, (keep >> so) & 1);
        while (surv) {
            int ls = __ffs(surv) - 1;
            surv &= surv - 1;
            int i = so * 32 + ls;
            float si = __shfl_sync(FULL, s[so], ls);
            float ei = __shfl_sync(FULL, e[so], ls);
            float li = ei - si;
#pragma unroll
            for (int t = 0; t < SLOTS; t++) {
                if (t >= nslots) break;
                int idx = t * 32 + lane;
                if (idx > i && ((keep >> t) & 1)) {
                    float inter = fmaxf(fminf(ei, e[t]) - fmaxf(si, s[t]), 0.0f);
                    float uni   = li + (e[t] - s[t]) - inter;
                    float iou   = inter / fmaxf(uni, 1e-8f);
                    if (iou > 0.5f) keep &= ~(1u << t);
                }
            }
            // drop same-slot boxes that were just suppressed
            surv &= __ballot_sync(FULL, (keep >> so) & 1);
        }
    }

    // Write masked outputs at global sorted positions
    float* obds = out + (size_t)NB * NCLIP * 3;
    float* osc  = obds + 2 * NN;
#pragma unroll
    for (int t = 0; t < SLOTS; t++) {
        if (t >= nslots) break;
        int idx = t * 32 + lane;
        if (idx < cnt) {
            int p = b * CAPB + idx;
            int g = g_bgr[p];
            float f = ((keep >> t) & 1) ? 1.0f : 0.0f;
            obds[2 * g]     = g_bs[p] * f;
            obds[2 * g + 1] = g_be[p] * f;
            osc[g]          = g_bsc[p] * f;
        }
    }
}

// ---------------------------------------------------------------------------
extern "C" void kernel_launch(void* const* d_in, const int* in_sizes, int n_in,
                              void* d_out, int out_size) {
    const float* gt    = (const float*)d_in[0];
    const float* pred  = (const float*)d_in[1];
    const float* score = (const float*)d_in[2];
    const int*   bidx  = (const int*)d_in[3];
    float* out = (float*)d_out;

    prep_kernel<<<2 * NB, 256>>>(gt, bidx, out);
    rank_partial_kernel<<<dim3(JCH, NN / 256), 256>>>(score);
    scatter_kernel<<<NN / 256, 256>>>(pred, score, bidx);
    nms_kernel<<<NB, 32>>>(out);
}

// round 5
// speedup vs baseline: 3.7485x; 2.1863x over previous
#include <cuda_runtime.h>

#define NB    32
#define NN    8192
#define NCLIP 256
#define JCH   16          // j-chunks for partial rank
#define JSZ   (NN / JCH)  // 512
#define CAPB  512         // per-batch capacity (mean 256, sd ~16)
#define NW    16          // bitmask words per column (CAPB/32)
#define FULL  0xffffffffu

// Scratch (__device__ globals; allocation-free rule)
__device__ int      g_off[NB + 1];
__device__ int      g_part[JCH * NN];
__device__ float    g_bs[NB * CAPB];
__device__ float    g_be[NB * CAPB];
__device__ float    g_bsc[NB * CAPB];
__device__ int      g_bgr[NB * CAPB];
__device__ unsigned g_sup[NB * CAPB * NW];   // suppression columns (1 MB)

// ---------------------------------------------------------------------------
// Kernel 1: blocks 0..31 -> gt_dist ; blocks 32..63 -> batch offsets g_off
// ---------------------------------------------------------------------------
__global__ void prep_kernel(const float* __restrict__ gt,
                            const int*   __restrict__ bidx,
                            float* __restrict__ out) {
    int blk = blockIdx.x;
    if (blk < NB) {
        int b = blk, c = threadIdx.x;
        float s = gt[2 * b];
        float e = gt[2 * b + 1];
        float len  = 256.0f * (e - s);
        float cen0 = 256.0f * s;
        float cen1 = 256.0f * e;
        float cen2 = 128.0f * (s + e);
        float sgS  = 0.25f * len;
        float sgM  = 0.21f * len;
        float inv2sS = 1.0f / (2.0f * sgS * sgS);
        float inv2sM = 1.0f / (2.0f * sgM * sgM);
        float fc = (float)c;
        float d0 = fc - cen0, d1 = fc - cen1, d2 = fc - cen2;
        float* o = out + ((size_t)b * NCLIP + c) * 3;
        o[0] = expf(-d0 * d0 * inv2sS);
        o[1] = expf(-d1 * d1 * inv2sS);
        o[2] = expf(-d2 * d2 * inv2sM);
    } else {
        int i = (blk - NB) * 256 + threadIdx.x;
        int b  = bidx[i];
        int pb = (i == 0) ? -1 : bidx[i - 1];
        for (int x = pb + 1; x <= b; x++) g_off[x] = i;
        if (i == NN - 1)
            for (int x = b + 1; x <= NB; x++) g_off[x] = NN;
    }
}

// ---------------------------------------------------------------------------
// Kernel 2: partial global rank over j-chunk jc.
// ---------------------------------------------------------------------------
__global__ void rank_partial_kernel(const float* __restrict__ score) {
    int jc = blockIdx.x;
    int i  = blockIdx.y * 256 + threadIdx.x;
    float si = score[i];
    const float4* s4 = (const float4*)score + jc * (JSZ / 4);
    int jbase = jc * JSZ;
    int r = 0;
#pragma unroll 8
    for (int t = 0; t < JSZ / 4; t++) {
        float4 v = s4[t];
        int j = jbase + 4 * t;
        r += (v.x > si) || (v.x == si && (j + 0) < i);
        r += (v.y > si) || (v.y == si && (j + 1) < i);
        r += (v.z > si) || (v.z == si && (j + 2) < i);
        r += (v.w > si) || (v.w == si && (j + 3) < i);
    }
    g_part[jc * NN + i] = r;
}

// ---------------------------------------------------------------------------
// Kernel 3: finalize ranks, within-batch rank, scatter to batch arrays.
// ---------------------------------------------------------------------------
__global__ void scatter_kernel(const float* __restrict__ pred,
                               const float* __restrict__ score,
                               const int*   __restrict__ bidx) {
    int i = blockIdx.x * 256 + threadIdx.x;
    int r = 0;
#pragma unroll
    for (int jc = 0; jc < JCH; jc++) r += g_part[jc * NN + i];

    float si = score[i];
    int b  = bidx[i];
    int ob = g_off[b], oe = g_off[b + 1];
    int wr = 0;
    for (int j = ob; j < oe; j++) {
        float sj = score[j];
        wr += (sj > si) || (sj == si && j < i);
    }
    if (wr < CAPB) {
        int p = b * CAPB + wr;
        g_bs[p]  = pred[2 * i];
        g_be[p]  = pred[2 * i + 1];
        g_bsc[p] = si;
        g_bgr[p] = r;
    }
}

// ---------------------------------------------------------------------------
// Kernel 4: build suppression bitmask columns.
// block = (column-group g of 32 columns, batch b); 256 threads = 32 cols x 8
// word-pairs. Column j gets word w = bits for rows i in [32w,32w+32), i<j.
// ---------------------------------------------------------------------------
__global__ void build_kernel() {
    int g = blockIdx.x;                 // 0..15
    int b = blockIdx.y;
    int cnt = g_off[b + 1] - g_off[b];
    if (cnt > CAPB) cnt = CAPB;
    if (32 * g >= cnt) return;

    int tid = threadIdx.x;
    int jl  = tid & 31;
    int wh  = tid >> 5;                 // 0..7

    __shared__ float ss[CAPB], se[CAPB], sl[CAPB];
    int rows = 32 * (g + 1);            // rows needed: i < 32g+32 (stale ok)
    for (int i = tid; i < rows; i += 256) {
        float s = g_bs[b * CAPB + i], e = g_be[b * CAPB + i];
        ss[i] = s; se[i] = e; sl[i] = e - s;
    }
    __syncthreads();

    int j = 32 * g + jl;
    if (j >= cnt) return;
    float sj = ss[j], ej = se[j], lj = sl[j];

    for (int w = wh; w <= g; w += 8) {
        unsigned word = 0;
        int base = 32 * w;
#pragma unroll
        for (int k = 0; k < 32; k++) {
            float si_ = ss[base + k], ei_ = se[base + k], li_ = sl[base + k];
            float interc = fmaxf(fminf(ej, ei_) - fmaxf(sj, si_), 0.0f);
            float uni = lj + li_ - interc;
            float um  = fmaxf(uni, 1e-8f);
            float diff = interc - 0.5f * um;       // 0.5*um exact
            bool sup;
            if (fabsf(diff) <= 1e-6f * um)         // borderline: exact ref path
                sup = (interc / um) > 0.5f;
            else
                sup = diff > 0.0f;
            if (sup) word |= 1u << k;
        }
        if (w == g) word &= (1u << jl) - 1u;        // only i < j
        g_sup[(b * CAPB + j) * NW + w] = word;
    }
}

// ---------------------------------------------------------------------------
// Kernel 5: serial greedy scan via bitmasks + ballot fixpoint; writeback.
// Warp per batch. keep[j] = 1 iff no kept i<j suppresses j.
// ---------------------------------------------------------------------------
__global__ void scan_kernel(float* __restrict__ out) {
    int b    = blockIdx.x;
    int lane = threadIdx.x;
    int cnt  = g_off[b + 1] - g_off[b];
    if (cnt > CAPB) cnt = CAPB;
    int nG = (cnt + 31) >> 5;

    __shared__ unsigned skeep[NW];

    for (int g = 0; g < nG; g++) {
        int j = 32 * g + lane;                        // j <= 511, in-bounds
        bool valid = j < cnt;
        const unsigned* col = &g_sup[(b * CAPB + j) * NW];
        unsigned dead = 0;
        for (int w = 0; w < g; w++)
            dead |= valid ? (col[w] & skeep[w]) : 0u;
        unsigned pend = valid ? col[g] : 0u;          // bits i < j only
        bool alive0 = valid && (dead == 0u);

        unsigned M = __ballot_sync(FULL, alive0);
        for (;;) {                                    // unique fixpoint = greedy
            unsigned Mn = __ballot_sync(FULL, alive0 && ((pend & M) == 0u));
            if (Mn == M) break;
            M = Mn;
        }
        skeep[g] = M;                                 // warp-uniform value
        __syncwarp();
    }

    // Writeback masked boxes/scores at global sorted positions
    float* obds = out + (size_t)NB * NCLIP * 3;
    float* osc  = obds + 2 * NN;
    for (int g = 0; g < nG; g++) {
        int idx = 32 * g + lane;
        if (idx < cnt) {
            int p  = b * CAPB + idx;
            int gr = g_bgr[p];
            float f = ((skeep[g] >> lane) & 1u) ? 1.0f : 0.0f;
            obds[2 * gr]     = g_bs[p] * f;
            obds[2 * gr + 1] = g_be[p] * f;
            osc[gr]          = g_bsc[p] * f;
        }
    }
}

// ---------------------------------------------------------------------------
extern "C" void kernel_launch(void* const* d_in, const int* in_sizes, int n_in,
                              void* d_out, int out_size) {
    const float* gt    = (const float*)d_in[0];
    const float* pred  = (const float*)d_in[1];
    const float* score = (const float*)d_in[2];
    const int*   bidx  = (const int*)d_in[3];
    float* out = (float*)d_out;

    prep_kernel<<<2 * NB, 256>>>(gt, bidx, out);
    rank_partial_kernel<<<dim3(JCH, NN / 256), 256>>>(score);
    scatter_kernel<<<NN / 256, 256>>>(pred, score, bidx);
    build_kernel<<<dim3(NW, NB), 256>>>();
    scan_kernel<<<NB, 32>>>(out);
}

// round 6
// speedup vs baseline: 4.1513x; 1.1075x over previous
#include <cuda_runtime.h>

#define NB    32
#define NN    8192
#define NCLIP 256
#define JCH   16          // j-chunks for partial rank
#define JSZ   (NN / JCH)  // 512
#define CAPB  512         // per-batch capacity (mean 256, max ~350)
#define NW    16          // mask words per column (CAPB/32)
#define FULL  0xffffffffu

// Scratch (__device__ globals; allocation-free rule)
__device__ int g_off[NB + 1];
__device__ int g_part[JCH * NN];

// ---------------------------------------------------------------------------
// K1: blocks 0..31 gt_dist | 32..63 batch offsets | 64..575 rank chunks
// ---------------------------------------------------------------------------
__global__ void k1_kernel(const float* __restrict__ gt,
                          const int*   __restrict__ bidx,
                          const float* __restrict__ score,
                          float* __restrict__ out) {
    int blk = blockIdx.x;
    int tid = threadIdx.x;
    if (blk < NB) {
        int b = blk, c = tid;
        float s = gt[2 * b];
        float e = gt[2 * b + 1];
        float len  = 256.0f * (e - s);
        float cen0 = 256.0f * s;
        float cen1 = 256.0f * e;
        float cen2 = 128.0f * (s + e);
        float sgS  = 0.25f * len;
        float sgM  = 0.21f * len;
        float inv2sS = 1.0f / (2.0f * sgS * sgS);
        float inv2sM = 1.0f / (2.0f * sgM * sgM);
        float fc = (float)c;
        float d0 = fc - cen0, d1 = fc - cen1, d2 = fc - cen2;
        float* o = out + ((size_t)b * NCLIP + c) * 3;
        o[0] = expf(-d0 * d0 * inv2sS);
        o[1] = expf(-d1 * d1 * inv2sS);
        o[2] = expf(-d2 * d2 * inv2sM);
    } else if (blk < 2 * NB) {
        int i = (blk - NB) * 256 + tid;
        int b  = bidx[i];
        int pb = (i == 0) ? -1 : bidx[i - 1];
        for (int x = pb + 1; x <= b; x++) g_off[x] = i;
        if (i == NN - 1)
            for (int x = b + 1; x <= NB; x++) g_off[x] = NN;
    } else {
        int q  = blk - 2 * NB;          // 0..511
        int jc = q & (JCH - 1);
        int i  = (q >> 4) * 256 + tid;
        float si = score[i];
        const float4* s4 = (const float4*)score + jc * (JSZ / 4);
        int jbase = jc * JSZ;
        int r = 0;
#pragma unroll 8
        for (int t = 0; t < JSZ / 4; t++) {
            float4 v = s4[t];
            int j = jbase + 4 * t;
            r += (v.x > si) || (v.x == si && (j + 0) < i);
            r += (v.y > si) || (v.y == si && (j + 1) < i);
            r += (v.z > si) || (v.z == si && (j + 2) < i);
            r += (v.w > si) || (v.w == si && (j + 3) < i);
        }
        g_part[jc * NN + i] = r;
    }
}

// ---------------------------------------------------------------------------
// K2: one CTA per batch — scatter + mask build + greedy scan + writeback,
// all in shared memory.
// ---------------------------------------------------------------------------
__global__ void k2_kernel(const float* __restrict__ pred,
                          const float* __restrict__ score,
                          float* __restrict__ out) {
    __shared__ float    rsc[CAPB];           // original-order batch scores
    __shared__ float    ss[CAPB], se[CAPB], sl[CAPB], ssc[CAPB];
    __shared__ int      sgr[CAPB];           // global rank per sorted slot
    __shared__ unsigned sup[NW * CAPB];      // word-major suppression masks
    __shared__ unsigned skeep[NW];

    int b   = blockIdx.x;
    int tid = threadIdx.x;
    int ob  = g_off[b], oe = g_off[b + 1];
    int cnt = oe - ob;
    if (cnt > CAPB) cnt = CAPB;
    if (cnt == 0) return;
    int nG = (cnt + 31) >> 5;

    // Load batch scores (original order)
    for (int t = tid; t < cnt; t += 256) rsc[t] = score[ob + t];
    __syncthreads();

    // Within-batch stable rank + global rank; scatter into sorted smem arrays
    for (int t = tid; t < cnt; t += 256) {
        float si = rsc[t];
        int wr = 0;
        for (int j = 0; j < cnt; j++) {
            float sj = rsc[j];
            wr += (sj > si) || (sj == si && j < t);
        }
        int i = ob + t;
        int r = 0;
#pragma unroll
        for (int jc = 0; jc < JCH; jc++) r += g_part[jc * NN + i];
        float s = pred[2 * i], e = pred[2 * i + 1];
        ss[wr]  = s;
        se[wr]  = e;
        sl[wr]  = e - s;
        ssc[wr] = si;
        sgr[wr] = r;
    }
    __syncthreads();

    // Build lower-triangle suppression masks: task p -> (group g, word w, col j)
    int Ttot = 16 * nG * (nG + 1);           // sum_g 32*(g+1)
    for (int p = tid; p < Ttot; p += 256) {
        int g = 0, base = 0;
        while (p >= base + 32 * (g + 1)) { base += 32 * (g + 1); g++; }
        int ofs = p - base;
        int w   = ofs >> 5;                  // 0..g
        int jl  = ofs & 31;
        int j   = 32 * g + jl;
        if (j >= cnt) continue;
        float sj = ss[j], ej = se[j], lj = sl[j];
        unsigned word = 0;
        int rb = 32 * w;
#pragma unroll
        for (int k = 0; k < 32; k++) {
            float si_ = ss[rb + k], ei_ = se[rb + k], li_ = sl[rb + k];
            float interc = fmaxf(fminf(ej, ei_) - fmaxf(sj, si_), 0.0f);
            float uni = lj + li_ - interc;
            float um  = fmaxf(uni, 1e-8f);
            float diff = interc - 0.5f * um;
            bool sp;
            if (fabsf(diff) <= 1e-6f * um) sp = (interc / um) > 0.5f;
            else                           sp = diff > 0.0f;
            if (sp) word |= 1u << k;
        }
        if (w == g) word &= (1u << jl) - 1u;     // only rows i < j
        sup[w * CAPB + j] = word;
    }
    __syncthreads();

    // Greedy scan via ballot fixpoint (warp 0)
    if (tid < 32) {
        int lane = tid;
        for (int g = 0; g < nG; g++) {
            int j = 32 * g + lane;
            bool valid = j < cnt;
            unsigned dead = 0;
            for (int w = 0; w < g; w++)
                dead |= valid ? (sup[w * CAPB + j] & skeep[w]) : 0u;
            unsigned pend = valid ? sup[g * CAPB + j] : 0u;
            bool alive0 = valid && (dead == 0u);
            unsigned M = __ballot_sync(FULL, alive0);
            for (;;) {
                unsigned Mn = __ballot_sync(FULL, alive0 && ((pend & M) == 0u));
                if (Mn == M) break;
                M = Mn;
            }
            skeep[g] = M;
            __syncwarp();
        }
    }
    __syncthreads();

    // Writeback at global sorted positions
    float* obds = out + (size_t)NB * NCLIP * 3;
    float* osc  = obds + 2 * NN;
    for (int t = tid; t < cnt; t += 256) {
        int gr = sgr[t];
        float f = ((skeep[t >> 5] >> (t & 31)) & 1u) ? 1.0f : 0.0f;
        obds[2 * gr]     = ss[t] * f;
        obds[2 * gr + 1] = se[t] * f;
        osc[gr]          = ssc[t] * f;
    }
}

// ---------------------------------------------------------------------------
extern "C" void kernel_launch(void* const* d_in, const int* in_sizes, int n_in,
                              void* d_out, int out_size) {
    const float* gt    = (const float*)d_in[0];
    const float* pred  = (const float*)d_in[1];
    const float* score = (const float*)d_in[2];
    const int*   bidx  = (const int*)d_in[3];
    float* out = (float*)d_out;

    k1_kernel<<<2 * NB + JCH * (NN / 256), 256>>>(gt, bidx, score, out);
    k2_kernel<<<NB, 256>>>(pred, score, out);
}